// round 3
// baseline (speedup 1.0000x reference)
#include <cuda_runtime.h>
#include <cstdint>

// Problem constants (fixed shapes from reference)
#define N_TOTAL 2048
#define T_DIM   128
#define F_DIM   32
#define K_DIM   32

#define NB      16                 // n-rows per block
#define TC      8                  // t-chunk per pipeline stage
#define CHUNKS  (T_DIM / TC)       // 16
#define THREADS 512                // 16 warps
#define NBLOCKS (N_TOTAL / NB)     // 128

// Shared memory layout (bytes):
//  [0      , 16K )  x buf 0 : [NB][TC][F] floats
//  [16K    , 32K )  x buf 1
//  [32K    , 64K )  c buf 0 : [K][TC][F] floats
//  [64K    , 96K )  c buf 1
#define XBUF_FLOATS (NB * TC * F_DIM)      // 4096
#define CBUF_FLOATS (K_DIM * TC * F_DIM)   // 8192
#define SMEM_BYTES  ((2 * XBUF_FLOATS + 2 * CBUF_FLOATS) * 4)  // 96 KB

__device__ __forceinline__ void cp_async16(uint32_t dst_smem, const void* src) {
    asm volatile("cp.async.cg.shared.global [%0], [%1], 16;\n"
                 :: "r"(dst_smem), "l"(src));
}
__device__ __forceinline__ void cp_commit() {
    asm volatile("cp.async.commit_group;\n" ::: "memory");
}
__device__ __forceinline__ void cp_wait1() {
    asm volatile("cp.async.wait_group 1;\n" ::: "memory");
}
__device__ __forceinline__ float fsqrt_approx(float v) {
    float r; asm("sqrt.approx.f32 %0, %1;" : "=f"(r) : "f"(v)); return r;
}
__device__ __forceinline__ float frcp_approx(float v) {
    float r; asm("rcp.approx.f32 %0, %1;" : "=f"(r) : "f"(v)); return r;
}

extern "C" __global__ void __launch_bounds__(THREADS, 1)
ts_clustering_kernel(const float* __restrict__ x,
                     const float* __restrict__ clusters,
                     float* __restrict__ out) {
    extern __shared__ float smem[];
    const uint32_t smem_u32 = (uint32_t)__cvta_generic_to_shared(smem);

    const int tid  = threadIdx.x;
    const int lane = tid & 31;          // = feature f
    const int w    = tid >> 5;          // warp 0..15
    const int wn   = w & 3;             // warp n-row  0..3
    const int wk   = w >> 2;            // warp k-row  0..3
    const int n0   = wn * 4;            // 4 n's per warp
    const int k0   = wk * 8;            // 8 k's per warp
    const int nBase = blockIdx.x * NB;

    // ---- async prefetch helpers -------------------------------------------
    // x chunk: NB rows, each (TC*F)=256 floats = 1KB contiguous in gmem (t,f inner)
    //          16KB total = 1024 x 16B, 2 per thread
    // c chunk: K rows of 1KB -> 32KB = 2048 x 16B, 4 per thread
    auto prefetch = [&](int ci, int buf) {
        const int t0 = ci * TC;
        const uint32_t xs_b = smem_u32 + (uint32_t)buf * (XBUF_FLOATS * 4);
        #pragma unroll
        for (int r = 0; r < 2; r++) {
            int idx = tid + r * THREADS;          // 0..1023
            int n   = idx >> 6;                   // 64 x 16B per n-row
            int rem = idx & 63;
            const char* src = (const char*)x
                + ((size_t)(nBase + n) * T_DIM + t0) * (F_DIM * 4) + (size_t)rem * 16;
            cp_async16(xs_b + (uint32_t)idx * 16, src);
        }
        const uint32_t cs_b = smem_u32 + (uint32_t)(2 * XBUF_FLOATS * 4)
                            + (uint32_t)buf * (CBUF_FLOATS * 4);
        #pragma unroll
        for (int r = 0; r < 4; r++) {
            int idx = tid + r * THREADS;          // 0..2047
            int k   = idx >> 6;
            int rem = idx & 63;
            const char* src = (const char*)clusters
                + ((size_t)k * T_DIM + t0) * (F_DIM * 4) + (size_t)rem * 16;
            cp_async16(cs_b + (uint32_t)idx * 16, src);
        }
    };

    // ---- accumulators ------------------------------------------------------
    float acc[4][8];
    #pragma unroll
    for (int i = 0; i < 4; i++)
        #pragma unroll
        for (int j = 0; j < 8; j++) acc[i][j] = 0.f;
    float sx2[4] = {0.f, 0.f, 0.f, 0.f};
    float sc2[8] = {0.f, 0.f, 0.f, 0.f, 0.f, 0.f, 0.f, 0.f};

    // ---- pipelined main loop ------------------------------------------------
    prefetch(0, 0);
    cp_commit();

    for (int ci = 0; ci < CHUNKS; ci++) {
        if (ci + 1 < CHUNKS) prefetch(ci + 1, (ci + 1) & 1);
        cp_commit();            // uniform group count (empty group on last iter)
        cp_wait1();             // chunk ci resident
        __syncthreads();

        const float* xs = smem + (ci & 1) * XBUF_FLOATS;                 // [NB][TC][F]
        const float* cs = smem + 2 * XBUF_FLOATS + (ci & 1) * CBUF_FLOATS; // [K][TC][F]

        #pragma unroll
        for (int t = 0; t < TC; t++) {
            float xr[4], cr[8];
            #pragma unroll
            for (int i = 0; i < 4; i++)
                xr[i] = xs[((n0 + i) * TC + t) * F_DIM + lane];
            #pragma unroll
            for (int j = 0; j < 8; j++)
                cr[j] = cs[((k0 + j) * TC + t) * F_DIM + lane];
            #pragma unroll
            for (int i = 0; i < 4; i++)
                #pragma unroll
                for (int j = 0; j < 8; j++)
                    acc[i][j] = fmaf(xr[i], cr[j], acc[i][j]);
            if (wk == 0) {
                #pragma unroll
                for (int i = 0; i < 4; i++) sx2[i] = fmaf(xr[i], xr[i], sx2[i]);
            }
            if (wn == 0) {
                #pragma unroll
                for (int j = 0; j < 8; j++) sc2[j] = fmaf(cr[j], cr[j], sc2[j]);
            }
        }
        __syncthreads();   // protect buffer (ci&1) before next prefetch overwrites it
    }

    // ---- epilogue: reuse smem for x2 / c2 / dist ----------------------------
    __syncthreads();
    float* x2s  = smem;                 // [NB][F]   512 floats
    float* c2s  = smem + 512;           // [K][F]   1024 floats
    float* dsts = smem + 512 + 1024;    // [NB][K]   512 floats

    if (wk == 0) {
        #pragma unroll
        for (int i = 0; i < 4; i++) x2s[(n0 + i) * F_DIM + lane] = sx2[i];
    }
    if (wn == 0) {
        #pragma unroll
        for (int j = 0; j < 8; j++) c2s[(k0 + j) * F_DIM + lane] = sc2[j];
    }
    __syncthreads();

    #pragma unroll
    for (int i = 0; i < 4; i++) {
        float x2v = x2s[(n0 + i) * F_DIM + lane];
        #pragma unroll
        for (int j = 0; j < 8; j++) {
            float sq = x2v + c2s[(k0 + j) * F_DIM + lane] - 2.0f * acc[i][j];
            sq = fmaxf(sq, 0.0f);
            float ed = fsqrt_approx(sq);
            // sum over f (lanes)
            #pragma unroll
            for (int off = 16; off > 0; off >>= 1)
                ed += __shfl_xor_sync(0xffffffffu, ed, off);
            if (lane == 0) dsts[(n0 + i) * K_DIM + (k0 + j)] = ed;
        }
    }
    __syncthreads();

    // ---- Student-t soft assignment + per-n normalization --------------------
    // warp w handles n = w (16 warps == NB); lane = k
    {
        float d = dsts[w * K_DIM + lane];
        float q = frcp_approx(fmaf(d, d, 1.0f));   // alpha = 1 -> q = 1/(1+d^2)
        float s = q;
        #pragma unroll
        for (int off = 16; off > 0; off >>= 1)
            s += __shfl_xor_sync(0xffffffffu, s, off);
        out[(size_t)(nBase + w) * K_DIM + lane] = q * frcp_approx(s);
    }
}

extern "C" void kernel_launch(void* const* d_in, const int* in_sizes, int n_in,
                              void* d_out, int out_size) {
    const float* x        = (const float*)d_in[0];   // (2048, 128, 32)
    const float* clusters = (const float*)d_in[1];   // (32, 128, 32)
    float* out            = (float*)d_out;           // (2048, 32)
    (void)in_sizes; (void)n_in; (void)out_size;

    cudaFuncSetAttribute(ts_clustering_kernel,
                         cudaFuncAttributeMaxDynamicSharedMemorySize, SMEM_BYTES);
    ts_clustering_kernel<<<NBLOCKS, THREADS, SMEM_BYTES>>>(x, clusters, out);
}

// round 4
// speedup vs baseline: 1.0768x; 1.0768x over previous
#include <cuda_runtime.h>
#include <cstdint>

// Shapes (fixed)
#define N_TOTAL 2048
#define T_DIM   128
#define F_DIM   32
#define K_DIM   32

#define NB      16                 // n per block
#define TC      8                  // t per pipeline chunk
#define CHUNKS  (T_DIM / TC)       // 16
#define THREADS 256                // 8 warps: 2 n-groups x 4 k-groups
#define NBLOCKS (N_TOTAL / NB)     // 128

#define XBUF_FLOATS (NB * TC * F_DIM)      // 4096 (16KB)
#define CBUF_FLOATS (K_DIM * TC * F_DIM)   // 8192 (32KB)
#define SMEM_BYTES  ((2 * XBUF_FLOATS + 2 * CBUF_FLOATS) * 4)  // 96KB

typedef unsigned long long u64;

__device__ __forceinline__ void cp_async16(uint32_t dst, const void* src) {
    asm volatile("cp.async.cg.shared.global [%0], [%1], 16;\n" :: "r"(dst), "l"(src));
}
__device__ __forceinline__ void cp_commit() {
    asm volatile("cp.async.commit_group;\n" ::: "memory");
}
__device__ __forceinline__ void cp_wait1() {
    asm volatile("cp.async.wait_group 1;\n" ::: "memory");
}
// Packed fp32x2 math (sm_103a)
__device__ __forceinline__ void ffma2(u64& d, u64 a, u64 b, u64 c) {
    asm("fma.rn.f32x2 %0, %1, %2, %3;" : "=l"(d) : "l"(a), "l"(b), "l"(c));
}
__device__ __forceinline__ u64 fadd2(u64 a, u64 b) {
    u64 d; asm("add.rn.f32x2 %0, %1, %2;" : "=l"(d) : "l"(a), "l"(b)); return d;
}
__device__ __forceinline__ float fsqrt_approx(float v) {
    float r; asm("sqrt.approx.f32 %0, %1;" : "=f"(r) : "f"(v)); return r;
}
__device__ __forceinline__ float frcp_approx(float v) {
    float r; asm("rcp.approx.f32 %0, %1;" : "=f"(r) : "f"(v)); return r;
}
__device__ __forceinline__ u64 lds64(const float* p) {
    return *reinterpret_cast<const u64*>(p);
}
__device__ __forceinline__ float lo32(u64 v) { return __uint_as_float((unsigned)v); }
__device__ __forceinline__ float hi32(u64 v) { return __uint_as_float((unsigned)(v >> 32)); }

// -2.0f packed twice
#define NEG2_PACKED 0xC0000000C0000000ULL

extern "C" __global__ void __launch_bounds__(THREADS, 1)
ts_clustering_kernel(const float* __restrict__ x,
                     const float* __restrict__ clusters,
                     float* __restrict__ out) {
    extern __shared__ float smem[];
    const uint32_t smem_u32 = (uint32_t)__cvta_generic_to_shared(smem);

    const int tid  = threadIdx.x;
    const int lane = tid & 31;
    const int w    = tid >> 5;          // warp 0..7
    const int wn   = w & 1;             // n-group 0..1 (8 n each)
    const int wk   = w >> 1;            // k-group 0..3 (8 k each)
    const int fp   = lane & 15;         // f-pair 0..15  (f = 2fp, 2fp+1)
    const int nsub = lane >> 4;         // n-half 0..1 (4 n each)
    const int nBase = blockIdx.x * NB;

    const int base_n = wn * 8 + nsub * 4;   // first of 4 n's for this lane
    const int base_k = wk * 8;              // first of 8 k's for this warp

    // ---- async prefetch ------------------------------------------------------
    auto prefetch = [&](int ci, int buf) {
        const int t0 = ci * TC;
        const uint32_t xs_b = smem_u32 + (uint32_t)buf * (XBUF_FLOATS * 4);
        #pragma unroll
        for (int r = 0; r < 4; r++) {                 // x: 1024 x 16B
            int idx = tid + r * THREADS;
            int n   = idx >> 6;
            int rem = idx & 63;
            const char* src = (const char*)x
                + ((size_t)(nBase + n) * T_DIM + t0) * (F_DIM * 4) + (size_t)rem * 16;
            cp_async16(xs_b + (uint32_t)idx * 16, src);
        }
        const uint32_t cs_b = smem_u32 + (uint32_t)(2 * XBUF_FLOATS * 4)
                            + (uint32_t)buf * (CBUF_FLOATS * 4);
        #pragma unroll
        for (int r = 0; r < 8; r++) {                 // c: 2048 x 16B
            int idx = tid + r * THREADS;
            int k   = idx >> 6;
            int rem = idx & 63;
            const char* src = (const char*)clusters
                + ((size_t)k * T_DIM + t0) * (F_DIM * 4) + (size_t)rem * 16;
            cp_async16(cs_b + (uint32_t)idx * 16, src);
        }
    };

    // ---- accumulators (packed f32x2 over the f-pair) -------------------------
    u64 acc[4][8];
    #pragma unroll
    for (int i = 0; i < 4; i++)
        #pragma unroll
        for (int j = 0; j < 8; j++) acc[i][j] = 0ULL;
    u64 sx2p[4] = {0ULL, 0ULL, 0ULL, 0ULL};                 // x^2 partials (t%4==wk)
    u64 sc2p[8] = {0ULL,0ULL,0ULL,0ULL,0ULL,0ULL,0ULL,0ULL}; // c^2 partials (t%2==wn)

    prefetch(0, 0);
    cp_commit();

    for (int ci = 0; ci < CHUNKS; ci++) {
        if (ci + 1 < CHUNKS) prefetch(ci + 1, (ci + 1) & 1);
        cp_commit();
        cp_wait1();
        __syncthreads();

        const float* xs = smem + (ci & 1) * XBUF_FLOATS;                    // [NB][TC][F]
        const float* cs = smem + 2 * XBUF_FLOATS + (ci & 1) * CBUF_FLOATS;  // [K][TC][F]
        const float* xp = xs + (base_n * TC) * F_DIM + 2 * fp;
        const float* cp = cs + (base_k * TC) * F_DIM + 2 * fp;

        #pragma unroll
        for (int t = 0; t < TC; t++) {
            u64 xr[4], cr[8];
            #pragma unroll
            for (int i = 0; i < 4; i++)
                xr[i] = lds64(xp + (i * TC + t) * F_DIM);
            #pragma unroll
            for (int j = 0; j < 8; j++)
                cr[j] = lds64(cp + (j * TC + t) * F_DIM);
            #pragma unroll
            for (int i = 0; i < 4; i++)
                #pragma unroll
                for (int j = 0; j < 8; j++)
                    ffma2(acc[i][j], xr[i], cr[j], acc[i][j]);
            if ((t & 3) == wk) {          // x^2 share for this warp's t-phase
                #pragma unroll
                for (int i = 0; i < 4; i++) ffma2(sx2p[i], xr[i], xr[i], sx2p[i]);
            }
            if ((t & 1) == wn) {          // c^2 share for this warp's t-phase
                #pragma unroll
                for (int j = 0; j < 8; j++) ffma2(sc2p[j], cr[j], cr[j], sc2p[j]);
            }
        }
        __syncthreads();
    }

    // ---- epilogue: combine partials, sqrt, reduce over f ----------------------
    __syncthreads();
    float* x2part = smem;                 // [4 wk][16 n][16 fp] pairs -> 2048 floats
    float* c2part = smem + 2048;          // [2 wn][32 k][16 fp] pairs -> 2048 floats
    float* dsts   = smem + 4096;          // [16 n][32 k] floats

    #pragma unroll
    for (int i = 0; i < 4; i++) {
        int n = base_n + i;
        *reinterpret_cast<u64*>(&x2part[2 * ((wk * 16 + n) * 16 + fp)]) = sx2p[i];
    }
    if (nsub == 0) {
        #pragma unroll
        for (int j = 0; j < 8; j++) {
            int k = base_k + j;
            *reinterpret_cast<u64*>(&c2part[2 * ((wn * 32 + k) * 16 + fp)]) = sc2p[j];
        }
    }
    __syncthreads();

    u64 c2p[8];
    #pragma unroll
    for (int j = 0; j < 8; j++) {
        int k = base_k + j;
        c2p[j] = fadd2(lds64(&c2part[2 * ((0 * 32 + k) * 16 + fp)]),
                       lds64(&c2part[2 * ((1 * 32 + k) * 16 + fp)]));
    }

    #pragma unroll
    for (int i = 0; i < 4; i++) {
        int n = base_n + i;
        u64 x2p = fadd2(fadd2(lds64(&x2part[2 * ((0 * 16 + n) * 16 + fp)]),
                              lds64(&x2part[2 * ((1 * 16 + n) * 16 + fp)])),
                        fadd2(lds64(&x2part[2 * ((2 * 16 + n) * 16 + fp)]),
                              lds64(&x2part[2 * ((3 * 16 + n) * 16 + fp)])));
        #pragma unroll
        for (int j = 0; j < 8; j++) {
            u64 s  = fadd2(x2p, c2p[j]);
            u64 sq;
            ffma2(sq, acc[i][j], NEG2_PACKED, s);   // x2 + c2 - 2*xc (both f's)
            float ed = fsqrt_approx(fmaxf(lo32(sq), 0.0f))
                     + fsqrt_approx(fmaxf(hi32(sq), 0.0f));
            #pragma unroll
            for (int off = 8; off > 0; off >>= 1)    // sum over 16 f-pairs
                ed += __shfl_xor_sync(0xffffffffu, ed, off);
            if (fp == 0) dsts[n * K_DIM + (base_k + j)] = ed;
        }
    }
    __syncthreads();

    // ---- Student-t + per-n normalization --------------------------------------
    #pragma unroll
    for (int n = w; n < NB; n += 8) {
        float d = dsts[n * K_DIM + lane];
        float q = frcp_approx(fmaf(d, d, 1.0f));     // alpha=1
        float sum = q;
        #pragma unroll
        for (int off = 16; off > 0; off >>= 1)
            sum += __shfl_xor_sync(0xffffffffu, sum, off);
        out[(size_t)(nBase + n) * K_DIM + lane] = q * frcp_approx(sum);
    }
}

extern "C" void kernel_launch(void* const* d_in, const int* in_sizes, int n_in,
                              void* d_out, int out_size) {
    const float* x        = (const float*)d_in[0];   // (2048, 128, 32)
    const float* clusters = (const float*)d_in[1];   // (32, 128, 32)
    float* out            = (float*)d_out;           // (2048, 32)
    (void)in_sizes; (void)n_in; (void)out_size;

    cudaFuncSetAttribute(ts_clustering_kernel,
                         cudaFuncAttributeMaxDynamicSharedMemorySize, SMEM_BYTES);
    ts_clustering_kernel<<<NBLOCKS, THREADS, SMEM_BYTES>>>(x, clusters, out);
}